// round 2
// baseline (speedup 1.0000x reference)
#include <cuda_runtime.h>

// Problem constants
#define Bsz 256      // batch
#define Isz 128      // in_units
#define Csz 1024     // in_channels
#define Nsz 512      // U*S = 32*16
#define NSPLIT 64    // split-K slices over C
#define CPS (Csz / NSPLIT)   // 16 c-values per slice

// GEMM tiling
#define BM 128
#define BN 128
#define BK 8
#define LDS_ 132     // padded smem row stride

// Scratch (static device globals — no allocation at runtime)
__device__ float g_xt[(size_t)Bsz * Csz * Isz];        // x transposed: (b, c, i)  134 MB
__device__ float g_part[(size_t)NSPLIT * Bsz * Nsz];   // split-K partials          32 MB

// ---------------------------------------------------------------------------
// Kernel 1: per-batch transpose x (B, I, C) -> xt (B, C, I)
// ---------------------------------------------------------------------------
__global__ void k_transpose(const float* __restrict__ x) {
    __shared__ float tile[32][33];
    int b  = blockIdx.z;
    int c0 = blockIdx.x * 32;
    int i0 = blockIdx.y * 32;
    const float* xb  = x    + (size_t)b * Isz * Csz;
    float*       xtb = g_xt + (size_t)b * Csz * Isz;
    int tx = threadIdx.x, ty = threadIdx.y;
#pragma unroll
    for (int j = 0; j < 32; j += 8)
        tile[ty + j][tx] = xb[(size_t)(i0 + ty + j) * Csz + (c0 + tx)];
    __syncthreads();
#pragma unroll
    for (int j = 0; j < 32; j += 8)
        xtb[(size_t)(c0 + ty + j) * Isz + (i0 + tx)] = tile[tx][ty + j];
}

// ---------------------------------------------------------------------------
// Kernel 2: split-K fp32 GEMM
//   s[m=b, n] += sum over k-slice of xt[b, k] * Wt[k, n]
//   k = c*128 + i ;  A = g_xt (row-major M x K, contiguous in k)
//   B block for c:  W + c*65536 is a contiguous (512, 128) row-major matrix
// ---------------------------------------------------------------------------
__global__ __launch_bounds__(256, 2)
void k_gemm(const float* __restrict__ W) {
    __shared__ float As[2][BK * LDS_];
    __shared__ float Bs[2][BK * LDS_];

    const int m0 = blockIdx.x * BM;
    const int n0 = blockIdx.y * BN;
    const int c0 = blockIdx.z * CPS;

    const int t    = threadIdx.x;
    const int lrow = t >> 1;        // 0..127 : row of A / row (n) of B to load
    const int kq   = (t & 1) * 4;   // 0 or 4 : k-offset of float4

    // A base: xt[b = m0+lrow][k = c0*128 + kq + ...]
    const float* Abase = g_xt + (size_t)(m0 + lrow) * (Csz * Isz)
                              + (size_t)c0 * Isz + kq;
    // B base: W[c0][n0+lrow][kq + ...]
    const float* Bbase = W + (size_t)c0 * (Nsz * Isz)
                           + (size_t)(n0 + lrow) * Isz + kq;

    float acc[8][8];
#pragma unroll
    for (int a = 0; a < 8; a++)
#pragma unroll
        for (int bb = 0; bb < 8; bb++) acc[a][bb] = 0.f;

    const int ty = t >> 4;   // 0..15
    const int tx = t & 15;   // 0..15

    const int NSTEP = CPS * (Isz / BK);  // 256 k-steps of 8

    // ---- prologue: load step 0 into buffer 0 ----
    float4 ra = *(const float4*)(Abase);
    float4 rb = *(const float4*)(Bbase);
    int buf = 0;
#pragma unroll
    for (int j = 0; j < 4; j++) {
        As[0][(kq + j) * LDS_ + lrow] = ((const float*)&ra)[j];
        Bs[0][(kq + j) * LDS_ + lrow] = ((const float*)&rb)[j];
    }
    __syncthreads();

    for (int step = 0; step < NSTEP; ++step) {
        const bool has_next = (step + 1 < NSTEP);
        if (has_next) {
            const int kk = (step + 1) * BK;     // linear k within slice
            const int ci = kk >> 7;             // c offset within slice
            const int ii = kk & 127;            // i offset
            ra = *(const float4*)(Abase + kk);  // A contiguous in k
            rb = *(const float4*)(Bbase + (size_t)ci * (Nsz * Isz) + ii);
        }

        // ---- compute current buffer ----
#pragma unroll
        for (int k = 0; k < BK; ++k) {
            float af[8], bf[8];
            float4 a0 = *(const float4*)&As[buf][k * LDS_ + ty * 8];
            float4 a1 = *(const float4*)&As[buf][k * LDS_ + ty * 8 + 4];
            float4 b0 = *(const float4*)&Bs[buf][k * LDS_ + tx * 8];
            float4 b1 = *(const float4*)&Bs[buf][k * LDS_ + tx * 8 + 4];
            af[0]=a0.x; af[1]=a0.y; af[2]=a0.z; af[3]=a0.w;
            af[4]=a1.x; af[5]=a1.y; af[6]=a1.z; af[7]=a1.w;
            bf[0]=b0.x; bf[1]=b0.y; bf[2]=b0.z; bf[3]=b0.w;
            bf[4]=b1.x; bf[5]=b1.y; bf[6]=b1.z; bf[7]=b1.w;
#pragma unroll
            for (int a = 0; a < 8; a++)
#pragma unroll
                for (int bb = 0; bb < 8; bb++)
                    acc[a][bb] = fmaf(af[a], bf[bb], acc[a][bb]);
        }

        if (has_next) {
            const int nb = buf ^ 1;
#pragma unroll
            for (int j = 0; j < 4; j++) {
                As[nb][(kq + j) * LDS_ + lrow] = ((const float*)&ra)[j];
                Bs[nb][(kq + j) * LDS_ + lrow] = ((const float*)&rb)[j];
            }
            __syncthreads();
            buf = nb;
        }
    }

    // ---- write partials (deterministic, each tile written exactly once) ----
    float* outp = g_part + (size_t)blockIdx.z * (Bsz * Nsz);
#pragma unroll
    for (int a = 0; a < 8; a++) {
        const int m = m0 + ty * 8 + a;
        float* row = outp + (size_t)m * Nsz + (n0 + tx * 8);
        *(float4*)(row)     = make_float4(acc[a][0], acc[a][1], acc[a][2], acc[a][3]);
        *(float4*)(row + 4) = make_float4(acc[a][4], acc[a][5], acc[a][6], acc[a][7]);
    }
}

// ---------------------------------------------------------------------------
// Kernel 3: reduce over split-K slices + squash epilogue
//   mag_sq[b, sidx] = sum_u s[b, u*16+sidx]^2   (squash is over the U axis)
//   out = s * mag / (1 + mag_sq)
// ---------------------------------------------------------------------------
__global__ void k_reduce_squash(float* __restrict__ out) {
    const int b = blockIdx.x;
    const int n = threadIdx.x;  // 0..511
    float s = 0.f;
    const float* p = g_part + (size_t)b * Nsz + n;
#pragma unroll 8
    for (int sl = 0; sl < NSPLIT; ++sl)
        s += p[(size_t)sl * (Bsz * Nsz)];

    __shared__ float sv[Nsz];
    sv[n] = s;
    __syncthreads();

    const int sidx = n & 15;
    float msq = 0.f;
#pragma unroll
    for (int u = 0; u < 32; ++u) {
        float v = sv[u * 16 + sidx];
        msq += v * v;
    }
    const float mag   = sqrtf(msq);
    const float scale = mag / (1.0f + msq);   // == msq/(1+msq) * 1/mag
    out[(size_t)b * Nsz + n] = s * scale;
}

// ---------------------------------------------------------------------------
extern "C" void kernel_launch(void* const* d_in, const int* in_sizes, int n_in,
                              void* d_out, int out_size) {
    const float* x = (const float*)d_in[0];   // (256, 128, 1024) fp32
    const float* W = (const float*)d_in[1];   // (1, 1024, 32, 16, 128) fp32
    float* out = (float*)d_out;               // (256, 32, 16, 1) fp32

    dim3 tgrid(Csz / 32, Isz / 32, Bsz);      // (32, 4, 256)
    k_transpose<<<tgrid, dim3(32, 8)>>>(x);

    dim3 ggrid(Bsz / BM, Nsz / BN, NSPLIT);   // (2, 4, 64) = 512 CTAs
    k_gemm<<<ggrid, 256>>>(W);

    k_reduce_squash<<<Bsz, Nsz>>>(out);
}

// round 6
// speedup vs baseline: 3.0412x; 3.0412x over previous
#include <cuda_runtime.h>
#include <cstdint>

// Problem constants
#define Bsz 256      // batch (GEMM M)
#define Isz 128      // in_units
#define Csz 1024     // in_channels
#define Nsz 512      // U*S (GEMM N)
#define NSPLIT 64    // split-K slices over C
#define CPS (Csz / NSPLIT)      // 16 c per slice
#define KSLICE (CPS * Isz)      // 2048 k per slice
#define BK 32
#define NSTAGE (KSLICE / BK)    // 64 stages

// smem: A/B tiles 128 rows x 32 floats, row stride 36 floats (conflict-free)
#define ASTRIDE 36
#define STG_FLOATS (128 * ASTRIDE)         // 4608 floats per operand tile
#define SMEM_FLOATS (4 * STG_FLOATS)       // 2 stages x (A + B)
#define SMEM_BYTES (SMEM_FLOATS * 4)       // 73728

// Scratch (static device globals — no runtime allocation)
__device__ float g_xt[(size_t)Bsz * Csz * Isz];        // x^T (b, c, i), tf32-rounded
__device__ float g_part[(size_t)NSPLIT * Bsz * Nsz];   // split-K partials

// ---------------------------------------------------------------------------
// Helpers (sm_80-era PTX only — target is compute_103 WITHOUT the 'a' suffix)
// ---------------------------------------------------------------------------
__device__ __forceinline__ uint32_t smem_u32(const void* p) {
    uint32_t a;
    asm("{ .reg .u64 t; cvta.to.shared.u64 t, %1; cvt.u32.u64 %0, t; }" : "=r"(a) : "l"(p));
    return a;
}
__device__ __forceinline__ float tf32_rn(float x) {
    float r;
    asm("cvt.rna.tf32.f32 %0, %1;" : "=f"(r) : "f"(x));
    return r;
}

#define CP_ASYNC16(dst, src) \
    asm volatile("cp.async.cg.shared.global [%0], [%1], 16;" :: "r"(dst), "l"(src))
#define CP_COMMIT()  asm volatile("cp.async.commit_group;" ::: "memory")
#define CP_WAIT(n)   asm volatile("cp.async.wait_group %0;" :: "n"(n) : "memory")

// m16n8k8 tf32 MMA (sm_80 PTX, runs on tensor pipe as legacy HMMA)
#define MMA_TF32(c, a, b) \
    asm volatile( \
        "mma.sync.aligned.m16n8k8.row.col.f32.tf32.tf32.f32 " \
        "{%0,%1,%2,%3}, {%4,%5,%6,%7}, {%8,%9}, {%0,%1,%2,%3};" \
        : "+f"((c)[0]), "+f"((c)[1]), "+f"((c)[2]), "+f"((c)[3]) \
        : "r"(__float_as_uint((a)[0])), "r"(__float_as_uint((a)[1])), \
          "r"(__float_as_uint((a)[2])), "r"(__float_as_uint((a)[3])), \
          "r"(__float_as_uint((b)[0])), "r"(__float_as_uint((b)[1])))

// ---------------------------------------------------------------------------
// Kernel 1: per-batch transpose x (B, I, C) -> xt (B, C, I), rounded to tf32
// ---------------------------------------------------------------------------
__global__ void k_transpose(const float* __restrict__ x) {
    __shared__ float tile[32][33];
    int b  = blockIdx.z;
    int c0 = blockIdx.x * 32;
    int i0 = blockIdx.y * 32;
    const float* xb  = x    + (size_t)b * Isz * Csz;
    float*       xtb = g_xt + (size_t)b * Csz * Isz;
    int tx = threadIdx.x, ty = threadIdx.y;
#pragma unroll
    for (int j = 0; j < 32; j += 8)
        tile[ty + j][tx] = xb[(size_t)(i0 + ty + j) * Csz + (c0 + tx)];
    __syncthreads();
#pragma unroll
    for (int j = 0; j < 32; j += 8)
        xtb[(size_t)(c0 + ty + j) * Isz + (i0 + tx)] = tf32_rn(tile[tx][ty + j]);
}

// ---------------------------------------------------------------------------
// Kernel 2: split-K tf32 GEMM via mma.sync (m16n8k8)
//   grid = (2 m-tiles, 4 n-tiles, 64 slices); CTA 128x128, BK=32
//   8 warps in 2x4 grid, warp tile 64x32 (4x4 mma tiles)
// ---------------------------------------------------------------------------
__global__ __launch_bounds__(256, 2)
void k_gemm_mma(const float* __restrict__ W) {
    extern __shared__ float sm[];
    const uint32_t smem_base = smem_u32(sm);

    const int tid  = threadIdx.x;
    const int wid  = tid >> 5;
    const int lane = tid & 31;
    const int g    = lane >> 2;   // group id (0..7)
    const int t    = lane & 3;    // thread-in-group

    const int warp_m = wid & 1;   // 0..1 -> 64-row block
    const int warp_n = wid >> 1;  // 0..3 -> 32-col block

    const int m0 = blockIdx.x * 128;
    const int n0 = blockIdx.y * 128;
    const int c0 = blockIdx.z * CPS;

    const float* aBase = g_xt + (size_t)m0 * (Csz * Isz) + (size_t)c0 * Isz;
    const float* wBase = W + (size_t)c0 * (Nsz * Isz) + (size_t)n0 * Isz;

    const int lr = tid >> 3;      // load row 0..31 (x8 per j)... see below
    const int lq = tid & 7;       // quad within row

    // loader: stage st into buffer bf
    auto load_stage = [&](int st, int bf) {
        const uint32_t dA = smem_base + (uint32_t)(bf * 2 * STG_FLOATS) * 4;
        const uint32_t dB = dA + (uint32_t)STG_FLOATS * 4;
        const float* asrc = aBase + st * 32;
        const float* bsrc = wBase + (size_t)(st >> 2) * (Nsz * Isz) + (st & 3) * 32;
#pragma unroll
        for (int j = 0; j < 4; j++) {
            int r = lr + j * 32;  // 0..127
            uint32_t so = (uint32_t)(r * ASTRIDE + lq * 4) * 4;
            CP_ASYNC16(dA + so, asrc + (size_t)r * (Csz * Isz) + lq * 4);
            CP_ASYNC16(dB + so, bsrc + (size_t)r * Isz + lq * 4);
        }
        CP_COMMIT();
    };

    float acc[4][4][4];
#pragma unroll
    for (int mt = 0; mt < 4; mt++)
#pragma unroll
        for (int nt = 0; nt < 4; nt++)
#pragma unroll
            for (int e = 0; e < 4; e++) acc[mt][nt][e] = 0.f;

    load_stage(0, 0);
    int buf = 0;

    for (int st = 0; st < NSTAGE; ++st) {
        if (st + 1 < NSTAGE) {
            load_stage(st + 1, buf ^ 1);
            CP_WAIT(1);
        } else {
            CP_WAIT(0);
        }
        __syncthreads();

        const float* cA = sm + buf * 2 * STG_FLOATS;
        const float* cB = cA + STG_FLOATS;

#pragma unroll
        for (int kk = 0; kk < 4; ++kk) {
            const int kb = kk * 8;
            float af[4][4];
#pragma unroll
            for (int mt = 0; mt < 4; mt++) {
                const int r0 = warp_m * 64 + mt * 16 + g;
                af[mt][0] = cA[r0 * ASTRIDE + kb + t];
                af[mt][1] = cA[(r0 + 8) * ASTRIDE + kb + t];
                af[mt][2] = cA[r0 * ASTRIDE + kb + t + 4];
                af[mt][3] = cA[(r0 + 8) * ASTRIDE + kb + t + 4];
            }
            float bfr[4][2];
#pragma unroll
            for (int nt = 0; nt < 4; nt++) {
                const int nn = warp_n * 32 + nt * 8 + g;
                bfr[nt][0] = tf32_rn(cB[nn * ASTRIDE + kb + t]);
                bfr[nt][1] = tf32_rn(cB[nn * ASTRIDE + kb + t + 4]);
            }
#pragma unroll
            for (int mt = 0; mt < 4; mt++)
#pragma unroll
                for (int nt = 0; nt < 4; nt++)
                    MMA_TF32(acc[mt][nt], af[mt], bfr[nt]);
        }
        __syncthreads();
        buf ^= 1;
    }

    // epilogue: deterministic partial writes (each element exactly once)
    float* dst = g_part + (size_t)blockIdx.z * (Bsz * Nsz);
#pragma unroll
    for (int mt = 0; mt < 4; mt++) {
        const int m = m0 + warp_m * 64 + mt * 16 + g;
#pragma unroll
        for (int nt = 0; nt < 4; nt++) {
            const int n = n0 + warp_n * 32 + nt * 8 + 2 * t;
            *(float2*)&dst[(size_t)m * Nsz + n] =
                make_float2(acc[mt][nt][0], acc[mt][nt][1]);
            *(float2*)&dst[(size_t)(m + 8) * Nsz + n] =
                make_float2(acc[mt][nt][2], acc[mt][nt][3]);
        }
    }
}

// ---------------------------------------------------------------------------
// Kernel 3: reduce over split-K slices + squash epilogue
// ---------------------------------------------------------------------------
__global__ void k_reduce_squash(float* __restrict__ out) {
    const int b = blockIdx.x;
    const int n = threadIdx.x;  // 0..511
    float s = 0.f;
    const float* p = g_part + (size_t)b * Nsz + n;
#pragma unroll 8
    for (int sl = 0; sl < NSPLIT; ++sl)
        s += p[(size_t)sl * (Bsz * Nsz)];

    __shared__ float sv[Nsz];
    sv[n] = s;
    __syncthreads();

    const int sidx = n & 15;
    float msq = 0.f;
#pragma unroll
    for (int u = 0; u < 32; ++u) {
        float v = sv[u * 16 + sidx];
        msq += v * v;
    }
    const float mag   = sqrtf(msq);
    const float scale = mag / (1.0f + msq);
    out[(size_t)b * Nsz + n] = s * scale;
}

// ---------------------------------------------------------------------------
extern "C" void kernel_launch(void* const* d_in, const int* in_sizes, int n_in,
                              void* d_out, int out_size) {
    const float* x = (const float*)d_in[0];   // (256, 128, 1024) fp32
    const float* W = (const float*)d_in[1];   // (1, 1024, 32, 16, 128) fp32
    float* out = (float*)d_out;               // (256, 32, 16, 1) fp32

    static bool attr_done = false;
    if (!attr_done) {
        cudaFuncSetAttribute(k_gemm_mma, cudaFuncAttributeMaxDynamicSharedMemorySize,
                             SMEM_BYTES);
        attr_done = true;
    }

    dim3 tgrid(Csz / 32, Isz / 32, Bsz);      // (32, 4, 256)
    k_transpose<<<tgrid, dim3(32, 8)>>>(x);

    dim3 ggrid(Bsz / 128, Nsz / 128, NSPLIT); // (2, 4, 64) = 512 CTAs
    k_gemm_mma<<<ggrid, 256, SMEM_BYTES>>>(W);

    k_reduce_squash<<<Bsz, Nsz>>>(out);
}

// round 8
// speedup vs baseline: 3.1297x; 1.0291x over previous
#include <cuda_runtime.h>
#include <cstdint>

// Problem constants
#define Bsz 256      // batch (GEMM M)
#define Isz 128      // in_units
#define Csz 1024     // in_channels
#define Nsz 512      // U*S (GEMM N)
#define NSPLIT 32    // split-K slices over C  -> grid 2x2x32 = 128 CTAs = 1 wave
#define CPS (Csz / NSPLIT)      // 32 c per slice
#define KSLICE (CPS * Isz)      // 4096 k per slice
#define BK 32
#define NSTAGE (KSLICE / BK)    // 128 stages

// CTA tile 128x256, 8 warps (2x4), warp tile 64x64
#define BM 128
#define BN 256

// smem row stride 36 floats (conflict-free for fragment pattern)
#define ASTRIDE 36
#define A_FLOATS (BM * ASTRIDE)                 // 4608
#define B_FLOATS (BN * ASTRIDE)                 // 9216
#define STG_FLOATS (A_FLOATS + B_FLOATS)        // 13824
#define SMEM_BYTES (2 * STG_FLOATS * 4)         // 110592

// Scratch (static device globals — no runtime allocation)
__device__ float g_xt[(size_t)Bsz * Csz * Isz];        // x^T (b, c, i), tf32-rounded
__device__ float g_part[(size_t)NSPLIT * Bsz * Nsz];   // split-K partials

// ---------------------------------------------------------------------------
// Helpers (sm_80-era PTX only — target is compute_103 WITHOUT the 'a' suffix)
// ---------------------------------------------------------------------------
__device__ __forceinline__ uint32_t smem_u32(const void* p) {
    uint32_t a;
    asm("{ .reg .u64 t; cvta.to.shared.u64 t, %1; cvt.u32.u64 %0, t; }" : "=r"(a) : "l"(p));
    return a;
}
__device__ __forceinline__ float tf32_rn(float x) {
    float r;
    asm("cvt.rna.tf32.f32 %0, %1;" : "=f"(r) : "f"(x));
    return r;
}

#define CP_ASYNC16(dst, src) \
    asm volatile("cp.async.cg.shared.global [%0], [%1], 16;" :: "r"(dst), "l"(src))
#define CP_COMMIT()  asm volatile("cp.async.commit_group;" ::: "memory")
#define CP_WAIT(n)   asm volatile("cp.async.wait_group %0;" :: "n"(n) : "memory")

// m16n8k8 tf32 MMA (sm_80 PTX, tensor pipe)
#define MMA_TF32(c, a, b) \
    asm volatile( \
        "mma.sync.aligned.m16n8k8.row.col.f32.tf32.tf32.f32 " \
        "{%0,%1,%2,%3}, {%4,%5,%6,%7}, {%8,%9}, {%0,%1,%2,%3};" \
        : "+f"((c)[0]), "+f"((c)[1]), "+f"((c)[2]), "+f"((c)[3]) \
        : "r"(__float_as_uint((a)[0])), "r"(__float_as_uint((a)[1])), \
          "r"(__float_as_uint((a)[2])), "r"(__float_as_uint((a)[3])), \
          "r"(__float_as_uint((b)[0])), "r"(__float_as_uint((b)[1])))

// ---------------------------------------------------------------------------
// Kernel 1: per-batch transpose x (B, I, C) -> xt (B, C, I), rounded to tf32
// ---------------------------------------------------------------------------
__global__ void k_transpose(const float* __restrict__ x) {
    __shared__ float tile[32][33];
    int b  = blockIdx.z;
    int c0 = blockIdx.x * 32;
    int i0 = blockIdx.y * 32;
    const float* xb  = x    + (size_t)b * Isz * Csz;
    float*       xtb = g_xt + (size_t)b * Csz * Isz;
    int tx = threadIdx.x, ty = threadIdx.y;
#pragma unroll
    for (int j = 0; j < 32; j += 8)
        tile[ty + j][tx] = xb[(size_t)(i0 + ty + j) * Csz + (c0 + tx)];
    __syncthreads();
#pragma unroll
    for (int j = 0; j < 32; j += 8)
        xtb[(size_t)(c0 + ty + j) * Isz + (i0 + tx)] = tf32_rn(tile[tx][ty + j]);
}

// ---------------------------------------------------------------------------
// Kernel 2: split-K tf32 GEMM via mma.sync (m16n8k8)
//   grid = (2 m-tiles, 2 n-tiles, 32 slices) = 128 CTAs (exactly one wave)
//   CTA 128x256, BK=32; 8 warps in 2x4; warp tile 64x64 (4x8 mma tiles)
// ---------------------------------------------------------------------------
__global__ __launch_bounds__(256, 1)
void k_gemm_mma(const float* __restrict__ W) {
    extern __shared__ float sm[];
    const uint32_t smem_base = smem_u32(sm);

    const int tid  = threadIdx.x;
    const int wid  = tid >> 5;
    const int lane = tid & 31;
    const int g    = lane >> 2;   // group id (0..7)
    const int t    = lane & 3;    // thread-in-group

    const int warp_m = wid & 1;   // 0..1 -> 64-row block
    const int warp_n = wid >> 1;  // 0..3 -> 64-col block

    const int m0 = blockIdx.x * BM;
    const int n0 = blockIdx.y * BN;
    const int c0 = blockIdx.z * CPS;

    const float* aBase = g_xt + (size_t)m0 * (Csz * Isz) + (size_t)c0 * Isz;
    const float* wBase = W + (size_t)c0 * (Nsz * Isz) + (size_t)n0 * Isz;

    const int lr = tid >> 3;      // 0..31
    const int lq = tid & 7;       // float4 index within 32-float row

    // loader: stage st into buffer bf
    auto load_stage = [&](int st, int bf) {
        const uint32_t dA = smem_base + (uint32_t)(bf * STG_FLOATS) * 4;
        const uint32_t dB = dA + (uint32_t)A_FLOATS * 4;
        const float* asrc = aBase + st * 32;
        const float* bsrc = wBase + (size_t)(st >> 2) * (Nsz * Isz) + (st & 3) * 32;
        // A: 128 rows
#pragma unroll
        for (int j = 0; j < 4; j++) {
            int r = lr + j * 32;
            uint32_t so = (uint32_t)(r * ASTRIDE + lq * 4) * 4;
            CP_ASYNC16(dA + so, asrc + (size_t)r * (Csz * Isz) + lq * 4);
        }
        // B: 256 rows
#pragma unroll
        for (int j = 0; j < 8; j++) {
            int r = lr + j * 32;
            uint32_t so = (uint32_t)(r * ASTRIDE + lq * 4) * 4;
            CP_ASYNC16(dB + so, bsrc + (size_t)r * Isz + lq * 4);
        }
        CP_COMMIT();
    };

    float acc[4][8][4];
#pragma unroll
    for (int mt = 0; mt < 4; mt++)
#pragma unroll
        for (int nt = 0; nt < 8; nt++)
#pragma unroll
            for (int e = 0; e < 4; e++) acc[mt][nt][e] = 0.f;

    load_stage(0, 0);
    int buf = 0;

    for (int st = 0; st < NSTAGE; ++st) {
        if (st + 1 < NSTAGE) {
            load_stage(st + 1, buf ^ 1);
            CP_WAIT(1);
        } else {
            CP_WAIT(0);
        }
        __syncthreads();

        const float* cA = sm + buf * STG_FLOATS;
        const float* cB = cA + A_FLOATS;

#pragma unroll
        for (int kk = 0; kk < 4; ++kk) {
            const int kb = kk * 8;
            float af[4][4];
#pragma unroll
            for (int mt = 0; mt < 4; mt++) {
                const int r0 = warp_m * 64 + mt * 16 + g;
                af[mt][0] = cA[r0 * ASTRIDE + kb + t];
                af[mt][1] = cA[(r0 + 8) * ASTRIDE + kb + t];
                af[mt][2] = cA[r0 * ASTRIDE + kb + t + 4];
                af[mt][3] = cA[(r0 + 8) * ASTRIDE + kb + t + 4];
            }
            float bfr[8][2];
#pragma unroll
            for (int nt = 0; nt < 8; nt++) {
                const int nn = warp_n * 64 + nt * 8 + g;
                bfr[nt][0] = tf32_rn(cB[nn * ASTRIDE + kb + t]);
                bfr[nt][1] = tf32_rn(cB[nn * ASTRIDE + kb + t + 4]);
            }
#pragma unroll
            for (int mt = 0; mt < 4; mt++)
#pragma unroll
                for (int nt = 0; nt < 8; nt++)
                    MMA_TF32(acc[mt][nt], af[mt], bfr[nt]);
        }
        __syncthreads();
        buf ^= 1;
    }

    // epilogue: deterministic partial writes (each element exactly once)
    float* dst = g_part + (size_t)blockIdx.z * (Bsz * Nsz);
#pragma unroll
    for (int mt = 0; mt < 4; mt++) {
        const int m = m0 + warp_m * 64 + mt * 16 + g;
#pragma unroll
        for (int nt = 0; nt < 8; nt++) {
            const int n = n0 + warp_n * 64 + nt * 8 + 2 * t;
            *(float2*)&dst[(size_t)m * Nsz + n] =
                make_float2(acc[mt][nt][0], acc[mt][nt][1]);
            *(float2*)&dst[(size_t)(m + 8) * Nsz + n] =
                make_float2(acc[mt][nt][2], acc[mt][nt][3]);
        }
    }
}

// ---------------------------------------------------------------------------
// Kernel 3: reduce over split-K slices + squash epilogue
// ---------------------------------------------------------------------------
__global__ void k_reduce_squash(float* __restrict__ out) {
    const int b = blockIdx.x;
    const int n = threadIdx.x;  // 0..511
    float s = 0.f;
    const float* p = g_part + (size_t)b * Nsz + n;
#pragma unroll 8
    for (int sl = 0; sl < NSPLIT; ++sl)
        s += p[(size_t)sl * (Bsz * Nsz)];

    __shared__ float sv[Nsz];
    sv[n] = s;
    __syncthreads();

    const int sidx = n & 15;
    float msq = 0.f;
#pragma unroll
    for (int u = 0; u < 32; ++u) {
        float v = sv[u * 16 + sidx];
        msq += v * v;
    }
    const float mag   = sqrtf(msq);
    const float scale = mag / (1.0f + msq);
    out[(size_t)b * Nsz + n] = s * scale;
}

// ---------------------------------------------------------------------------
extern "C" void kernel_launch(void* const* d_in, const int* in_sizes, int n_in,
                              void* d_out, int out_size) {
    const float* x = (const float*)d_in[0];   // (256, 128, 1024) fp32
    const float* W = (const float*)d_in[1];   // (1, 1024, 32, 16, 128) fp32
    float* out = (float*)d_out;               // (256, 32, 16, 1) fp32

    static bool attr_done = false;
    if (!attr_done) {
        cudaFuncSetAttribute(k_gemm_mma, cudaFuncAttributeMaxDynamicSharedMemorySize,
                             SMEM_BYTES);
        attr_done = true;
    }

    dim3 tgrid(Csz / 32, Isz / 32, Bsz);      // (32, 4, 256)
    k_transpose<<<tgrid, dim3(32, 8)>>>(x);

    dim3 ggrid(Bsz / BM, Nsz / BN, NSPLIT);   // (2, 2, 32) = 128 CTAs
    k_gemm_mma<<<ggrid, 256, SMEM_BYTES>>>(W);

    k_reduce_squash<<<Bsz, Nsz>>>(out);
}

// round 9
// speedup vs baseline: 4.8103x; 1.5370x over previous
#include <cuda_runtime.h>
#include <cuda_fp16.h>
#include <cstdint>

// Problem constants
#define Bsz 256      // batch (GEMM M)
#define Isz 128      // in_units
#define Csz 1024     // in_channels
#define Nsz 512      // U*S (GEMM N)
#define NSPLIT 32    // split-K slices -> grid (2,2,32) = 128 CTAs = 1 wave
#define CPS (Csz / NSPLIT)      // 32 c per slice
#define KSLICE (CPS * Isz)      // 4096 k per slice
#define BK 32                   // k per stage (2 x k16 MMA steps)
#define NSTAGE (KSLICE / BK)    // 128 stages

// CTA tile 128x256, 8 warps (2x4), warp tile 64x64
#define BM 128
#define BN 256

// smem rows padded to 40 halfs (80 B) -> conflict-free fragment loads
#define RSTRIDE 40
#define A_HALFS (BM * RSTRIDE)              // 5120
#define B_HALFS (BN * RSTRIDE)              // 10240
#define STG_HALFS (A_HALFS + B_HALFS)       // 15360
#define SMEM_BYTES (2 * STG_HALFS * 2)      // 61440

// Scratch (static device globals — no runtime allocation)
__device__ __half g_xh[(size_t)Bsz * Csz * Isz];       // x^T (b, c, i) in fp16
__device__ float  g_part[(size_t)NSPLIT * Bsz * Nsz];  // split-K partials

// ---------------------------------------------------------------------------
// Helpers (sm_70/80-era PTX only — target is compute_103 WITHOUT 'a')
// ---------------------------------------------------------------------------
__device__ __forceinline__ uint32_t smem_u32(const void* p) {
    uint32_t a;
    asm("{ .reg .u64 t; cvta.to.shared.u64 t, %1; cvt.u32.u64 %0, t; }" : "=r"(a) : "l"(p));
    return a;
}

#define CP_ASYNC16(dst, src) \
    asm volatile("cp.async.cg.shared.global [%0], [%1], 16;" :: "r"(dst), "l"(src))
#define CP_COMMIT()  asm volatile("cp.async.commit_group;" ::: "memory")
#define CP_WAIT(n)   asm volatile("cp.async.wait_group %0;" :: "n"(n) : "memory")

// m16n8k16 fp16 MMA, fp32 accumulate (sm_70 base PTX)
#define MMA_F16(c, a, b) \
    asm volatile( \
        "mma.sync.aligned.m16n8k16.row.col.f32.f16.f16.f32 " \
        "{%0,%1,%2,%3}, {%4,%5,%6,%7}, {%8,%9}, {%0,%1,%2,%3};" \
        : "+f"((c)[0]), "+f"((c)[1]), "+f"((c)[2]), "+f"((c)[3]) \
        : "r"((a)[0]), "r"((a)[1]), "r"((a)[2]), "r"((a)[3]), \
          "r"((b)[0]), "r"((b)[1]))

// ---------------------------------------------------------------------------
// Kernel 1: per-batch transpose x (B, I, C) -> xh (B, C, I) in fp16
// ---------------------------------------------------------------------------
__global__ void k_transpose(const float* __restrict__ x) {
    __shared__ float tile[32][33];
    int b  = blockIdx.z;
    int c0 = blockIdx.x * 32;
    int i0 = blockIdx.y * 32;
    const float* xb  = x    + (size_t)b * Isz * Csz;
    __half*      xtb = g_xh + (size_t)b * Csz * Isz;
    int tx = threadIdx.x, ty = threadIdx.y;
#pragma unroll
    for (int j = 0; j < 32; j += 8)
        tile[ty + j][tx] = xb[(size_t)(i0 + ty + j) * Csz + (c0 + tx)];
    __syncthreads();
#pragma unroll
    for (int j = 0; j < 32; j += 8)
        xtb[(size_t)(c0 + ty + j) * Isz + (i0 + tx)] = __float2half_rn(tile[tx][ty + j]);
}

// ---------------------------------------------------------------------------
// Kernel 2: split-K fp16 GEMM via mma.sync m16n8k16 (fp32 accum)
//   grid = (2 m, 2 n, 32 slices) = 128 CTAs; CTA 128x256; warp tile 64x64
//   A (fp16) via cp.async; B from W fp32 via LDG.128 -> cvt -> STS.64
// ---------------------------------------------------------------------------
__global__ __launch_bounds__(256, 1)
void k_gemm_mma(const float* __restrict__ W) {
    extern __shared__ __half sm[];
    const uint32_t smem_base = smem_u32(sm);

    const int tid  = threadIdx.x;
    const int wid  = tid >> 5;
    const int lane = tid & 31;
    const int g    = lane >> 2;   // group id (0..7)
    const int t    = lane & 3;    // thread-in-group

    const int warp_m = wid & 1;   // 0..1 -> 64-row block
    const int warp_n = wid >> 1;  // 0..3 -> 64-col block

    const int m0 = blockIdx.x * BM;
    const int n0 = blockIdx.y * BN;
    const int c0 = blockIdx.z * CPS;

    const __half* aBase = g_xh + (size_t)m0 * (Csz * Isz) + (size_t)c0 * Isz;
    const float*  wBase = W + (size_t)c0 * (Nsz * Isz) + (size_t)n0 * Isz;

    // A loader indices: 128 rows x 4 chunks of 16B (8 halfs)
    const int a_row = tid >> 2;   // 0..63 (+64 on j=1)
    const int a_ch  = tid & 3;    // 16B chunk
    // B loader indices: 256 rows x 8 chunks of float4 (4 floats -> 4 halfs)
    const int b_row = tid >> 3;   // 0..31 (+32*j)
    const int b_ch  = tid & 7;

    auto a_issue = [&](int st, int bf) {
        const uint32_t dA = smem_base + (uint32_t)(bf * STG_HALFS) * 2;
        const __half* asrc = aBase + st * BK;
#pragma unroll
        for (int j = 0; j < 2; j++) {
            int r = a_row + j * 64;
            uint32_t so = (uint32_t)(r * RSTRIDE + a_ch * 8) * 2;
            CP_ASYNC16(dA + so, asrc + (size_t)r * (Csz * Isz) + a_ch * 8);
        }
        CP_COMMIT();
    };

    float4 bpf[8];
    auto b_ldg = [&](int st) {
        const float* bsrc = wBase + (size_t)(st >> 2) * (Nsz * Isz) + (st & 3) * BK;
#pragma unroll
        for (int j = 0; j < 8; j++) {
            int r = b_row + j * 32;
            bpf[j] = *(const float4*)(bsrc + (size_t)r * Isz + b_ch * 4);
        }
    };
    auto b_sts = [&](int bf) {
        __half* dB = sm + bf * STG_HALFS + A_HALFS;
#pragma unroll
        for (int j = 0; j < 8; j++) {
            int r = b_row + j * 32;
            __half2 p0 = __floats2half2_rn(bpf[j].x, bpf[j].y);
            __half2 p1 = __floats2half2_rn(bpf[j].z, bpf[j].w);
            *(__half2*)(dB + r * RSTRIDE + b_ch * 4)     = p0;
            *(__half2*)(dB + r * RSTRIDE + b_ch * 4 + 2) = p1;
        }
    };

    float acc[4][8][4];
#pragma unroll
    for (int mt = 0; mt < 4; mt++)
#pragma unroll
        for (int nt = 0; nt < 8; nt++)
#pragma unroll
            for (int e = 0; e < 4; e++) acc[mt][nt][e] = 0.f;

    // prologue: stage 0
    b_ldg(0);
    a_issue(0, 0);
    b_sts(0);
    CP_WAIT(0);
    __syncthreads();
    int buf = 0;

    for (int st = 0; st < NSTAGE; ++st) {
        const bool has_next = (st + 1 < NSTAGE);
        if (has_next) {
            b_ldg(st + 1);            // LDG latency overlapped by compute below
            a_issue(st + 1, buf ^ 1);
        }

        const __half* cA = sm + buf * STG_HALFS;
        const __half* cB = cA + A_HALFS;

#pragma unroll
        for (int kk = 0; kk < 2; ++kk) {
            const int kb = kk * 16;
            uint32_t af[4][4];
#pragma unroll
            for (int mt = 0; mt < 4; mt++) {
                const int r0 = warp_m * 64 + mt * 16 + g;
                const __half* p0 = cA + r0 * RSTRIDE + kb + 2 * t;
                const __half* p1 = cA + (r0 + 8) * RSTRIDE + kb + 2 * t;
                af[mt][0] = *(const uint32_t*)p0;
                af[mt][1] = *(const uint32_t*)p1;
                af[mt][2] = *(const uint32_t*)(p0 + 8);
                af[mt][3] = *(const uint32_t*)(p1 + 8);
            }
            uint32_t bfr[8][2];
#pragma unroll
            for (int nt = 0; nt < 8; nt++) {
                const int nn = warp_n * 64 + nt * 8 + g;
                const __half* p = cB + nn * RSTRIDE + kb + 2 * t;
                bfr[nt][0] = *(const uint32_t*)p;
                bfr[nt][1] = *(const uint32_t*)(p + 8);
            }
#pragma unroll
            for (int mt = 0; mt < 4; mt++)
#pragma unroll
                for (int nt = 0; nt < 8; nt++)
                    MMA_F16(acc[mt][nt], af[mt], bfr[nt]);
        }

        if (has_next) {
            b_sts(buf ^ 1);
            CP_WAIT(0);
        }
        __syncthreads();
        buf ^= 1;
    }

    // epilogue: deterministic partial writes
    float* dst = g_part + (size_t)blockIdx.z * (Bsz * Nsz);
#pragma unroll
    for (int mt = 0; mt < 4; mt++) {
        const int m = m0 + warp_m * 64 + mt * 16 + g;
#pragma unroll
        for (int nt = 0; nt < 8; nt++) {
            const int n = n0 + warp_n * 64 + nt * 8 + 2 * t;
            *(float2*)&dst[(size_t)m * Nsz + n] =
                make_float2(acc[mt][nt][0], acc[mt][nt][1]);
            *(float2*)&dst[(size_t)(m + 8) * Nsz + n] =
                make_float2(acc[mt][nt][2], acc[mt][nt][3]);
        }
    }
}

// ---------------------------------------------------------------------------
// Kernel 3: reduce over split-K slices + squash epilogue
// ---------------------------------------------------------------------------
__global__ void k_reduce_squash(float* __restrict__ out) {
    const int b = blockIdx.x;
    const int n = threadIdx.x;  // 0..511
    float s = 0.f;
    const float* p = g_part + (size_t)b * Nsz + n;
#pragma unroll 8
    for (int sl = 0; sl < NSPLIT; ++sl)
        s += p[(size_t)sl * (Bsz * Nsz)];

    __shared__ float sv[Nsz];
    sv[n] = s;
    __syncthreads();

    const int sidx = n & 15;
    float msq = 0.f;
#pragma unroll
    for (int u = 0; u < 32; ++u) {
        float v = sv[u * 16 + sidx];
        msq += v * v;
    }
    const float mag   = sqrtf(msq);
    const float scale = mag / (1.0f + msq);
    out[(size_t)b * Nsz + n] = s * scale;
}

// ---------------------------------------------------------------------------
extern "C" void kernel_launch(void* const* d_in, const int* in_sizes, int n_in,
                              void* d_out, int out_size) {
    const float* x = (const float*)d_in[0];   // (256, 128, 1024) fp32
    const float* W = (const float*)d_in[1];   // (1, 1024, 32, 16, 128) fp32
    float* out = (float*)d_out;               // (256, 32, 16, 1) fp32

    static bool attr_done = false;
    if (!attr_done) {
        cudaFuncSetAttribute(k_gemm_mma, cudaFuncAttributeMaxDynamicSharedMemorySize,
                             SMEM_BYTES);
        attr_done = true;
    }

    dim3 tgrid(Csz / 32, Isz / 32, Bsz);      // (32, 4, 256)
    k_transpose<<<tgrid, dim3(32, 8)>>>(x);

    dim3 ggrid(Bsz / BM, Nsz / BN, NSPLIT);   // (2, 2, 32) = 128 CTAs
    k_gemm_mma<<<ggrid, 256, SMEM_BYTES>>>(W);

    k_reduce_squash<<<Bsz, Nsz>>>(out);
}